// round 10
// baseline (speedup 1.0000x reference)
#include <cuda_runtime.h>
#include <cstdint>

#define NC  5
#define TPB 256

__device__ __forceinline__ float fast_ex2(float x) {
    float y; asm("ex2.approx.f32 %0, %1;" : "=f"(y) : "f"(x)); return y;
}
__device__ __forceinline__ float fast_lg2(float x) {
    float y; asm("lg2.approx.f32 %0, %1;" : "=f"(y) : "f"(x)); return y;
}
__device__ __forceinline__ float fast_rcp(float x) {
    float y; asm("rcp.approx.f32 %0, %1;" : "=f"(y) : "f"(x)); return y;
}
__device__ __forceinline__ float fast_rsq(float x) {
    float y; asm("rsqrt.approx.f32 %0, %1;" : "=f"(y) : "f"(x)); return y;
}

// h(t) = t*mu(t) - log2 Z(t) + C2 (log2 domain), C2=(ln5-eps)/ln2, increasing.
// p(t) = softmax(t ln q). Feasible (lam=0) iff h(1) <= 0, then p = q/sum(q).
#define C2CONST 2.1776498f     // (ln5 - 0.1)/ln2
#define LN2SQ   0.48045302f    // ln2^2
#define LN2CU   0.33302465f    // ln2^3
#define RLN2    1.44269504f    // 1/ln2
#define SQ2EPS  0.44721360f    // sqrt(2*eps)

// Solve h(t)=0 on (0,1): cubic-Taylor init + 3 safeguarded Newton steps.
__device__ __forceinline__ float solve_row(const float L[NC]) {
    float s1 = 0.f, s2 = 0.f, s3 = 0.f;
    #pragma unroll
    for (int j = 0; j < NC; j++) {
        float lj = L[j];
        s1 += lj; s2 = fmaf(lj, lj, s2); s3 = fmaf(lj * lj, lj, s3);
    }
    float m   = s1 * 0.2f;
    float e2  = s2 * 0.2f;
    float V   = fmaxf(LN2SQ * (e2 - m * m), 1e-9f);
    float m3  = LN2CU * fmaf(s3, 0.2f, fmaf(-3.f * m, e2, 2.f * m * m * m));
    float tl  = SQ2EPS * fast_rsq(V);
    float den = fmaxf(fmaf(0.6666667f * m3, tl, V), 1e-9f);
    float tc  = fminf(0.95f, fmaxf(SQ2EPS * fast_rsq(den), 1e-4f));

    float lo = 0.f, hi = 1.f;
    #pragma unroll
    for (int it = 0; it < 3; ++it) {
        float S = 0.f, A = 0.f, B = 0.f;
        #pragma unroll
        for (int j = 0; j < NC; j++) {
            float e  = fast_ex2(tc * L[j]);
            float el = e * L[j];
            S += e; A = fmaf(e, L[j], A); B = fmaf(el, L[j], B);
        }
        float r  = fast_rcp(S);
        float mu = A * r;
        float v  = fmaf(B, r, -(mu * mu));
        float h  = fmaf(tc, mu, C2CONST - fast_lg2(S));
        float hp = tc * v;
        bool pos = (h > 0.f);
        hi = pos ? tc : hi;
        lo = pos ? lo : tc;
        float tn = fmaf(-h * RLN2, fast_rcp(hp), tc);
        bool ok = (tn > lo) && (tn < hi);   // false also on NaN
        tc = ok ? tn : 0.5f * (lo + hi);
    }
    return tc;
}

// ---------------- Vectorized kernel: 4 rows/thread, float4 I/O ----------------
__global__ void __launch_bounds__(TPB) kl_proj_vec4(
    const float4* __restrict__ x4,
    const float*  __restrict__ W,
    const float*  __restrict__ b,
    float4* __restrict__ o4)
{
    __shared__ float sW[NC * NC];
    __shared__ float sb[NC];
    if (threadIdx.x < NC * NC) sW[threadIdx.x] = W[threadIdx.x];
    if (threadIdx.x < NC)      sb[threadIdx.x] = b[threadIdx.x];
    __syncthreads();

    size_t g = (size_t)blockIdx.x * TPB + threadIdx.x;
    const float4* xin = x4 + g * 5;

    float a[20];
    #pragma unroll
    for (int i = 0; i < 5; i++) {
        float4 v = xin[i];
        a[4*i+0] = v.x; a[4*i+1] = v.y; a[4*i+2] = v.z; a[4*i+3] = v.w;
    }

    float S1[4];
    #pragma unroll
    for (int r = 0; r < 4; r++) {
        // q = x W^T + b (q in [0.1, 3.1]); L = log2 q
        float q[NC], L[NC];
        float s = 0.f, A = 0.f;
        #pragma unroll
        for (int j = 0; j < NC; j++) {
            float qq = sb[j];
            #pragma unroll
            for (int k = 0; k < NC; k++) qq = fmaf(a[r*NC + k], sW[j*NC + k], qq);
            float lj = fast_lg2(qq);
            q[j] = qq; L[j] = lj;
            s += qq; A = fmaf(qq, lj, A);
        }
        float h1 = A * fast_rcp(s) - fast_lg2(s) + C2CONST;
        bool feas = (h1 <= 0.f);

        if (!__all_sync(0xffffffffu, feas)) {        // rare (~2.5% of warp-rows)
            float t = feas ? 1.f : solve_row(L);
            float S = 0.f;
            #pragma unroll
            for (int j = 0; j < NC; j++) { q[j] = fast_ex2(t * L[j]); S += q[j]; }
            s = S;
        }
        S1[r] = s;
        #pragma unroll
        for (int j = 0; j < NC; j++) a[r*NC + j] = q[j];   // p numerators
    }

    float rr[4];
    #pragma unroll
    for (int r = 0; r < 4; r++) rr[r] = fast_rcp(S1[r]);
    #pragma unroll
    for (int i = 0; i < 20; i++) a[i] *= rr[i / NC];

    float4* oo = o4 + g * 5;
    #pragma unroll
    for (int i = 0; i < 5; i++)
        oo[i] = make_float4(a[4*i+0], a[4*i+1], a[4*i+2], a[4*i+3]);
}

// ---------------- Scalar fallback: 1 row/thread (any alignment) ----------------
__global__ void __launch_bounds__(TPB) kl_proj_scalar(
    const float* __restrict__ x,
    const float* __restrict__ W,
    const float* __restrict__ b,
    float* __restrict__ out,
    int n)
{
    __shared__ float sW[NC * NC];
    __shared__ float sb[NC];
    if (threadIdx.x < NC * NC) sW[threadIdx.x] = W[threadIdx.x];
    if (threadIdx.x < NC)      sb[threadIdx.x] = b[threadIdx.x];
    __syncthreads();

    int row = blockIdx.x * blockDim.x + threadIdx.x;
    if (row >= n) return;

    float xv[NC];
    #pragma unroll
    for (int k = 0; k < NC; k++) xv[k] = x[row * NC + k];

    float q[NC], L[NC];
    float s = 0.f, A = 0.f;
    #pragma unroll
    for (int j = 0; j < NC; j++) {
        float qq = sb[j];
        #pragma unroll
        for (int k = 0; k < NC; k++) qq = fmaf(xv[k], sW[j*NC + k], qq);
        float lj = fast_lg2(qq);
        q[j] = qq; L[j] = lj;
        s += qq; A = fmaf(qq, lj, A);
    }
    float h1 = A * fast_rcp(s) - fast_lg2(s) + C2CONST;
    bool feas = (h1 <= 0.f);

    if (!__all_sync(0xffffffffu, feas)) {
        float t = feas ? 1.f : solve_row(L);
        float S = 0.f;
        #pragma unroll
        for (int j = 0; j < NC; j++) { q[j] = fast_ex2(t * L[j]); S += q[j]; }
        s = S;
    }
    float r = fast_rcp(s);
    #pragma unroll
    for (int j = 0; j < NC; j++) out[row * NC + j] = q[j] * r;
}

extern "C" void kernel_launch(void* const* d_in, const int* in_sizes, int n_in,
                              void* d_out, int out_size) {
    const float* x = (const float*)d_in[0];
    const float* W = (const float*)d_in[1];
    const float* b = (const float*)d_in[2];
    float* out = (float*)d_out;
    int n = in_sizes[0] / NC;   // 2,097,152 rows

    bool aligned = ((((uintptr_t)x) | ((uintptr_t)out)) & 15u) == 0
                   && (n % (TPB * 4)) == 0;
    if (aligned) {
        int blocks = n / (TPB * 4);
        kl_proj_vec4<<<blocks, TPB>>>((const float4*)x, W, b, (float4*)out);
    } else {
        int blocks = (n + TPB - 1) / TPB;
        kl_proj_scalar<<<blocks, TPB>>>(x, W, b, out, n);
    }
}

// round 11
// speedup vs baseline: 1.0122x; 1.0122x over previous
#include <cuda_runtime.h>
#include <cstdint>

#define NC  5
#define TPB 256

__device__ __forceinline__ float fast_ex2(float x) {
    float y; asm("ex2.approx.f32 %0, %1;" : "=f"(y) : "f"(x)); return y;
}
__device__ __forceinline__ float fast_lg2(float x) {
    float y; asm("lg2.approx.f32 %0, %1;" : "=f"(y) : "f"(x)); return y;
}
__device__ __forceinline__ float fast_rcp(float x) {
    float y; asm("rcp.approx.f32 %0, %1;" : "=f"(y) : "f"(x)); return y;
}
__device__ __forceinline__ float fast_rsq(float x) {
    float y; asm("rsqrt.approx.f32 %0, %1;" : "=f"(y) : "f"(x)); return y;
}

// h(t) = t*mu(t) - log2 Z(t) + C2 (log2 domain), C2=(ln5-eps)/ln2, increasing.
// p(t) = softmax(t ln q). Feasible (lam=0) iff h(1) <= 0, then p = q/sum(q).
#define C2CONST 2.1776498f     // (ln5 - 0.1)/ln2
#define LN2SQ   0.48045302f    // ln2^2
#define LN2CU   0.33302465f    // ln2^3
#define RLN2    1.44269504f    // 1/ln2
#define SQ2EPS  0.44721360f    // sqrt(2*eps)

// Solve h(t)=0 on (0,1): cubic-Taylor init + 3 safeguarded Newton steps.
__device__ __forceinline__ float solve_row(const float L[NC]) {
    float s1 = 0.f, s2 = 0.f, s3 = 0.f;
    #pragma unroll
    for (int j = 0; j < NC; j++) {
        float lj = L[j];
        s1 += lj; s2 = fmaf(lj, lj, s2); s3 = fmaf(lj * lj, lj, s3);
    }
    float m   = s1 * 0.2f;
    float e2  = s2 * 0.2f;
    float V   = fmaxf(LN2SQ * (e2 - m * m), 1e-9f);
    float m3  = LN2CU * fmaf(s3, 0.2f, fmaf(-3.f * m, e2, 2.f * m * m * m));
    float tl  = SQ2EPS * fast_rsq(V);
    float den = fmaxf(fmaf(0.6666667f * m3, tl, V), 1e-9f);
    float tc  = fminf(0.95f, fmaxf(SQ2EPS * fast_rsq(den), 1e-4f));

    float lo = 0.f, hi = 1.f;
    #pragma unroll
    for (int it = 0; it < 3; ++it) {
        float S = 0.f, A = 0.f, B = 0.f;
        #pragma unroll
        for (int j = 0; j < NC; j++) {
            float e  = fast_ex2(tc * L[j]);
            float el = e * L[j];
            S += e; A = fmaf(e, L[j], A); B = fmaf(el, L[j], B);
        }
        float r  = fast_rcp(S);
        float mu = A * r;
        float v  = fmaf(B, r, -(mu * mu));
        float h  = fmaf(tc, mu, C2CONST - fast_lg2(S));
        float hp = tc * v;
        bool pos = (h > 0.f);
        hi = pos ? tc : hi;
        lo = pos ? lo : tc;
        float tn = fmaf(-h * RLN2, fast_rcp(hp), tc);
        bool ok = (tn > lo) && (tn < hi);   // false also on NaN
        tc = ok ? tn : 0.5f * (lo + hi);
    }
    return tc;
}

// ---------------- Vectorized kernel: 4 rows/thread, float4 I/O ----------------
__global__ void __launch_bounds__(TPB) kl_proj_vec4(
    const float4* __restrict__ x4,
    const float*  __restrict__ W,
    const float*  __restrict__ b,
    float4* __restrict__ o4)
{
    __shared__ float sW[NC * NC];
    __shared__ float sb[NC];
    if (threadIdx.x < NC * NC) sW[threadIdx.x] = W[threadIdx.x];
    if (threadIdx.x < NC)      sb[threadIdx.x] = b[threadIdx.x];
    __syncthreads();

    size_t g = (size_t)blockIdx.x * TPB + threadIdx.x;
    const float4* xin = x4 + g * 5;

    float a[20];
    #pragma unroll
    for (int i = 0; i < 5; i++) {
        float4 v = xin[i];
        a[4*i+0] = v.x; a[4*i+1] = v.y; a[4*i+2] = v.z; a[4*i+3] = v.w;
    }

    // ---- Phase 1: all 4 rows' linear + feasibility (independent -> ILP) ----
    float inv[4];
    bool  feas[4];
    #pragma unroll
    for (int r = 0; r < 4; r++) {
        float q[NC];
        float s = 0.f, A = 0.f;
        #pragma unroll
        for (int j = 0; j < NC; j++) {
            float qq = sb[j];
            #pragma unroll
            for (int k = 0; k < NC; k++) qq = fmaf(a[r*NC + k], sW[j*NC + k], qq);
            q[j] = qq;
            s += qq;
            A = fmaf(qq, fast_lg2(qq), A);   // lg2 transient, not stored
        }
        float ir = fast_rcp(s);
        float h1 = A * ir - fast_lg2(s) + C2CONST;
        feas[r] = (h1 <= 0.f);
        inv[r]  = ir;
        #pragma unroll
        for (int j = 0; j < NC; j++) a[r*NC + j] = q[j];   // q overwrites x
    }

    // ---- Phase 2: single vote; rare projection branch ----
    bool all4 = feas[0] && feas[1] && feas[2] && feas[3];
    if (!__all_sync(0xffffffffu, all4)) {
        #pragma unroll
        for (int r = 0; r < 4; r++) {
            if (__any_sync(0xffffffffu, !feas[r])) {
                if (!feas[r]) {
                    float L[NC];
                    #pragma unroll
                    for (int j = 0; j < NC; j++) L[j] = fast_lg2(a[r*NC + j]);
                    float t = solve_row(L);
                    float S = 0.f;
                    #pragma unroll
                    for (int j = 0; j < NC; j++) {
                        float e = fast_ex2(t * L[j]);
                        a[r*NC + j] = e;
                        S += e;
                    }
                    inv[r] = fast_rcp(S);
                }
            }
        }
    }

    // ---- Phase 3: normalize + vec4 store ----
    #pragma unroll
    for (int i = 0; i < 20; i++) a[i] *= inv[i / NC];

    float4* oo = o4 + g * 5;
    #pragma unroll
    for (int i = 0; i < 5; i++)
        oo[i] = make_float4(a[4*i+0], a[4*i+1], a[4*i+2], a[4*i+3]);
}

// ---------------- Scalar fallback: 1 row/thread (any alignment) ----------------
__global__ void __launch_bounds__(TPB) kl_proj_scalar(
    const float* __restrict__ x,
    const float* __restrict__ W,
    const float* __restrict__ b,
    float* __restrict__ out,
    int n)
{
    __shared__ float sW[NC * NC];
    __shared__ float sb[NC];
    if (threadIdx.x < NC * NC) sW[threadIdx.x] = W[threadIdx.x];
    if (threadIdx.x < NC)      sb[threadIdx.x] = b[threadIdx.x];
    __syncthreads();

    int row = blockIdx.x * blockDim.x + threadIdx.x;
    if (row >= n) return;

    float xv[NC];
    #pragma unroll
    for (int k = 0; k < NC; k++) xv[k] = x[row * NC + k];

    float q[NC];
    float s = 0.f, A = 0.f;
    #pragma unroll
    for (int j = 0; j < NC; j++) {
        float qq = sb[j];
        #pragma unroll
        for (int k = 0; k < NC; k++) qq = fmaf(xv[k], sW[j*NC + k], qq);
        q[j] = qq;
        s += qq;
        A = fmaf(qq, fast_lg2(qq), A);
    }
    float ir = fast_rcp(s);
    float h1 = A * ir - fast_lg2(s) + C2CONST;
    bool feas = (h1 <= 0.f);

    if (!__all_sync(0xffffffffu, feas)) {
        if (!feas) {
            float L[NC];
            #pragma unroll
            for (int j = 0; j < NC; j++) L[j] = fast_lg2(q[j]);
            float t = solve_row(L);
            float S = 0.f;
            #pragma unroll
            for (int j = 0; j < NC; j++) { q[j] = fast_ex2(t * L[j]); S += q[j]; }
            ir = fast_rcp(S);
        }
    }
    #pragma unroll
    for (int j = 0; j < NC; j++) out[row * NC + j] = q[j] * ir;
}

extern "C" void kernel_launch(void* const* d_in, const int* in_sizes, int n_in,
                              void* d_out, int out_size) {
    const float* x = (const float*)d_in[0];
    const float* W = (const float*)d_in[1];
    const float* b = (const float*)d_in[2];
    float* out = (float*)d_out;
    int n = in_sizes[0] / NC;   // 2,097,152 rows

    bool aligned = ((((uintptr_t)x) | ((uintptr_t)out)) & 15u) == 0
                   && (n % (TPB * 4)) == 0;
    if (aligned) {
        int blocks = n / (TPB * 4);
        kl_proj_vec4<<<blocks, TPB>>>((const float4*)x, W, b, (float4*)out);
    } else {
        int blocks = (n + TPB - 1) / TPB;
        kl_proj_scalar<<<blocks, TPB>>>(x, W, b, out, n);
    }
}